// round 1
// baseline (speedup 1.0000x reference)
#include <cuda_runtime.h>
#include <math.h>

// Problem constants
#define PP    256      // num paths (batch)
#define LMAX  64       // max path length
#define IDIM  512      // input dim
#define HDIM  1024     // hidden dim
#define G4    4096     // 4*H gates
#define ODIM  2

// GEMM tiling
#define BM 64
#define BN 64
#define BK 16
#define TM 8
#define TN 4
// 128 threads per block: 16 (N) x 8 (M)

// ---------------- device scratch (no runtime allocation allowed) ----------------
__device__ float d_gx[(size_t)LMAX * PP * G4];   // precomputed x_t @ W_ih^T + b   [l*P+p][4096]
__device__ float d_gates[PP * G4];
__device__ float d_h[PP * HDIM];
__device__ float d_c[PP * HDIM];
__device__ float d_fh[PP * HDIM];
__device__ float d_v[PP * HDIM];
__device__ float d_attn[PP * HDIM];

// ---------------------------------------------------------------------------
// NT SGEMM: C[M,N] = A[M,K] * B[N,K]^T  (+bias)(+bias2)(+D elementwise)
// EMBED mode: A rows are gathered from emb_table via paths; row r = l*P + p,
// token = paths[p*LMAX + l]. Blocks whose 64 paths are all past their length
// are skipped entirely (their gx rows are never consumed meaningfully).
// ---------------------------------------------------------------------------
__global__ void __launch_bounds__(128)
gemm_nt(const float* __restrict__ A, const float* __restrict__ B,
        float* __restrict__ C, int M, int N, int K,
        const float* __restrict__ bias, const float* __restrict__ bias2,
        const float* __restrict__ D,
        const int* __restrict__ paths, const int* __restrict__ lengths)
{
    __shared__ __align__(16) float As[BK][BM];
    __shared__ __align__(16) float Bs[BK][BN];

    const int tid = threadIdx.x;
    const int m0 = blockIdx.y * BM;
    const int n0 = blockIdx.x * BN;

    if (paths != nullptr) {
        // dead-block skip: all rows of this block share timestep l
        const int l  = m0 / PP;
        const int p0 = m0 % PP;
        __shared__ int need;
        if (tid == 0) need = 0;
        __syncthreads();
        if (tid < BM && lengths[p0 + tid] > l) need = 1;
        __syncthreads();
        if (!need) return;
    }

    const int tx = tid & 15;   // 0..15  -> N
    const int ty = tid >> 4;   // 0..7   -> M

    float acc[TM][TN];
#pragma unroll
    for (int i = 0; i < TM; i++)
#pragma unroll
        for (int j = 0; j < TN; j++) acc[i][j] = 0.f;

    for (int k0 = 0; k0 < K; k0 += BK) {
        __syncthreads();
        // load A tile (64x16) and B tile (64x16): 2 float4 each per thread
#pragma unroll
        for (int it = 0; it < 2; it++) {
            const int e  = tid * 2 + it;     // 0..255 float4 slots
            const int m  = e >> 2;
            const int kq = e & 3;
            const float* arow;
            if (paths != nullptr) {
                const int gr = m0 + m;
                const int l = gr / PP;
                const int p = gr % PP;
                const int tok = paths[p * LMAX + l];
                arow = A + (size_t)tok * K;
            } else {
                arow = A + (size_t)(m0 + m) * K;
            }
            const float4 av = *(const float4*)(arow + k0 + kq * 4);
            As[kq * 4 + 0][m] = av.x; As[kq * 4 + 1][m] = av.y;
            As[kq * 4 + 2][m] = av.z; As[kq * 4 + 3][m] = av.w;

            const float4 bv = *(const float4*)(B + (size_t)(n0 + m) * K + k0 + kq * 4);
            Bs[kq * 4 + 0][m] = bv.x; Bs[kq * 4 + 1][m] = bv.y;
            Bs[kq * 4 + 2][m] = bv.z; Bs[kq * 4 + 3][m] = bv.w;
        }
        __syncthreads();

#pragma unroll
        for (int kk = 0; kk < BK; ++kk) {
            const float4 a0 = *(const float4*)&As[kk][ty * TM];
            const float4 a1 = *(const float4*)&As[kk][ty * TM + 4];
            const float4 b0 = *(const float4*)&Bs[kk][tx * TN];
            const float a[TM] = {a0.x, a0.y, a0.z, a0.w, a1.x, a1.y, a1.z, a1.w};
            const float b[TN] = {b0.x, b0.y, b0.z, b0.w};
#pragma unroll
            for (int i = 0; i < TM; i++)
#pragma unroll
                for (int j = 0; j < TN; j++)
                    acc[i][j] = fmaf(a[i], b[j], acc[i][j]);
        }
    }

    // epilogue
    const int nc = n0 + tx * TN;
#pragma unroll
    for (int i = 0; i < TM; i++) {
        const int m = m0 + ty * TM + i;
        const size_t off = (size_t)m * N + nc;
        float4 r = make_float4(acc[i][0], acc[i][1], acc[i][2], acc[i][3]);
        if (bias)  { r.x += bias[nc+0];  r.y += bias[nc+1];  r.z += bias[nc+2];  r.w += bias[nc+3]; }
        if (bias2) { r.x += bias2[nc+0]; r.y += bias2[nc+1]; r.z += bias2[nc+2]; r.w += bias2[nc+3]; }
        if (D) {
            const float4 dv = *(const float4*)(D + off);
            r.x += dv.x; r.y += dv.y; r.z += dv.z; r.w += dv.w;
        }
        *(float4*)(C + off) = r;
    }
}

// ---------------------------------------------------------------------------
__global__ void zero_hc()
{
    const int i = blockIdx.x * blockDim.x + threadIdx.x;   // 0..262143
    d_h[i] = 0.f;
    d_c[i] = 0.f;
}

__device__ __forceinline__ float sigf(float x) { return 1.f / (1.f + expf(-x)); }

__global__ void lstm_update(const int* __restrict__ lengths, int t)
{
    const int idx = blockIdx.x * blockDim.x + threadIdx.x; // 0..262143
    const int p = idx >> 10;
    const int j = idx & 1023;
    const float* g = d_gates + (size_t)p * G4;
    const float i_s = sigf(g[j]);
    const float f_s = sigf(g[j + 1024]);
    const float g_t = tanhf(g[j + 2048]);
    const float o_s = sigf(g[j + 3072]);
    const float c = f_s * d_c[idx] + i_s * g_t;
    d_c[idx] = c;
    const float h = o_s * tanhf(c);
    d_h[idx] = h;
    if (lengths[p] - 1 == t) d_fh[idx] = h;
}

// maxpool over P paths + final linear (OUT=2) + sigmoid
__global__ void __launch_bounds__(1024)
pool_out(const float* __restrict__ Wlin, const float* __restrict__ blin,
         float* __restrict__ out)
{
    const int j = threadIdx.x;  // 0..1023
    float m = -INFINITY;
#pragma unroll 8
    for (int p = 0; p < PP; p++)
        m = fmaxf(m, d_attn[p * HDIM + j]);

    __shared__ float s0[1024];
    __shared__ float s1[1024];
    s0[j] = m * Wlin[j];
    s1[j] = m * Wlin[HDIM + j];
    __syncthreads();
    for (int s = 512; s > 0; s >>= 1) {
        if (j < s) { s0[j] += s0[j + s]; s1[j] += s1[j + s]; }
        __syncthreads();
    }
    if (j == 0) {
        out[0] = sigf(s0[0] + blin[0]);
        out[1] = sigf(s1[0] + blin[1]);
    }
}

// ---------------------------------------------------------------------------
extern "C" void kernel_launch(void* const* d_in, const int* in_sizes, int n_in,
                              void* d_out, int out_size)
{
    const int*   paths  = (const int*)  d_in[0];
    const int*   lens   = (const int*)  d_in[1];
    const float* emb    = (const float*)d_in[2];
    const float* W_ih   = (const float*)d_in[3];
    const float* W_hh   = (const float*)d_in[4];
    const float* b_ih   = (const float*)d_in[5];
    const float* b_hh   = (const float*)d_in[6];
    const float* W_in   = (const float*)d_in[7];
    const float* b_in   = (const float*)d_in[8];
    const float* W_out  = (const float*)d_in[9];
    const float* b_out  = (const float*)d_in[10];
    const float* W_lin  = (const float*)d_in[11];
    const float* b_lin  = (const float*)d_in[12];
    float* out = (float*)d_out;

    float *gx, *gates, *h, *fh, *v, *attn;
    cudaGetSymbolAddress((void**)&gx,    d_gx);
    cudaGetSymbolAddress((void**)&gates, d_gates);
    cudaGetSymbolAddress((void**)&h,     d_h);
    cudaGetSymbolAddress((void**)&fh,    d_fh);
    cudaGetSymbolAddress((void**)&v,     d_v);
    cudaGetSymbolAddress((void**)&attn,  d_attn);

    const dim3 blk(128);

    // init state
    zero_hc<<<(PP * HDIM) / 256, 256>>>();

    // Precompute gx[l*P+p][:] = emb[paths[p][l]] @ W_ih^T + (b_ih + b_hh)
    gemm_nt<<<dim3(G4 / BN, (LMAX * PP) / BM), blk>>>(
        emb, W_ih, gx, LMAX * PP, G4, IDIM, b_ih, b_hh, nullptr, paths, lens);

    // Recurrence: 64 sequential steps
    for (int t = 0; t < LMAX; t++) {
        gemm_nt<<<dim3(G4 / BN, PP / BM), blk>>>(
            h, W_hh, gates, PP, G4, HDIM, nullptr, nullptr,
            gx + (size_t)t * PP * G4, nullptr, nullptr);
        lstm_update<<<(PP * HDIM) / 256, 256>>>(lens, t);
    }

    // Degenerate attention (seq_len=1 => attn weight == 1 => ctx == v):
    // v = final_h @ W_v^T + b_v   (W_v = rows [2H,3H) of W_in)
    gemm_nt<<<dim3(HDIM / BN, PP / BM), blk>>>(
        fh, W_in + (size_t)2 * HDIM * HDIM, v, PP, HDIM, HDIM,
        b_in + 2 * HDIM, nullptr, nullptr, nullptr, nullptr);

    // attn_out = v @ W_out^T + b_out
    gemm_nt<<<dim3(HDIM / BN, PP / BM), blk>>>(
        v, W_out, attn, PP, HDIM, HDIM, b_out, nullptr, nullptr, nullptr, nullptr);

    // maxpool over paths + final linear + sigmoid
    pool_out<<<1, 1024>>>(W_lin, b_lin, out);
}

// round 3
// speedup vs baseline: 1.3439x; 1.3439x over previous
#include <cuda_runtime.h>
#include <math.h>
#include <stdint.h>

// Problem constants
#define PP    256      // num paths (batch)
#define LMAX  64       // max path length
#define IDIM  512      // input dim
#define HDIM  1024     // hidden dim
#define G4    4096     // 4*H gates

// GEMM tiling (tf32 mma.sync m16n8k8)
#define BM 128
#define BN 128
#define BK 16
#define NTHREADS 256   // 8 warps: 2 (M) x 4 (N), warp tile 64x32

// ---------------- device scratch (no runtime allocation allowed) ----------------
__device__ float d_gx[(size_t)LMAX * PP * G4];   // x_t @ W_ih^T + b, row = l*PP+p
__device__ float d_gates[PP * G4];
__device__ float d_h[PP * HDIM];
__device__ float d_c[PP * HDIM];
__device__ float d_fh[PP * HDIM];
__device__ float d_v[PP * HDIM];
__device__ float d_attn[PP * HDIM];

__device__ __forceinline__ uint32_t f2tf32(float x) {
    uint32_t u;
    asm("cvt.rna.tf32.f32 %0, %1;" : "=r"(u) : "f"(x));
    return u;
}

// ---------------------------------------------------------------------------
// NT GEMM via tf32 tensor cores: C[M,N] = A[M,K] * B[N,K]^T (+bias)(+bias2)(+D)
// Optional gather mode: A row r -> emb row paths[(r%PP)*LMAX + (r/PP)]; blocks
// whose 128 paths are all past their length are skipped.
// ---------------------------------------------------------------------------
__global__ void __launch_bounds__(NTHREADS, 1)
gemm_tf32_nt(const float* __restrict__ A, const float* __restrict__ B,
             float* __restrict__ C, int M, int N, int K,
             const float* __restrict__ bias, const float* __restrict__ bias2,
             const float* __restrict__ D,
             const int* __restrict__ paths, const int* __restrict__ lengths)
{
    __shared__ uint32_t As[2][BK][BM + 4];
    __shared__ uint32_t Bs[2][BK][BN + 4];
    __shared__ int need;

    const int tid = threadIdx.x;
    const int m0 = blockIdx.y * BM;
    const int n0 = blockIdx.x * BN;

    if (paths != nullptr) {
        // all 128 rows of this block share timestep l (PP=256 is a multiple of BM)
        const int l  = m0 / PP;
        const int p0 = m0 % PP;
        if (tid == 0) need = 0;
        __syncthreads();
        if (tid < BM && lengths[p0 + tid] > l) need = 1;
        __syncthreads();
        if (!need) return;
    }

    const int wid = tid >> 5;
    const int lane = tid & 31;
    const int warpM = (wid & 1) * 64;   // 2 warps along M
    const int warpN = (wid >> 1) * 32;  // 4 warps along N
    const int g  = lane >> 2;           // groupID 0..7
    const int tg = lane & 3;            // thread-in-group 0..3

    // ---- global load mapping: thread loads 2 float4 of A and 2 of B per tile
    const int lrow = tid >> 2;          // 0..63
    const int kq   = (tid & 3) * 4;     // float4 slot within BK
    const float *pa0, *pa1;
    if (paths != nullptr) {
        const int r0 = m0 + lrow, r1 = m0 + lrow + 64;
        const int t0 = paths[(r0 % PP) * LMAX + (r0 / PP)];
        const int t1 = paths[(r1 % PP) * LMAX + (r1 / PP)];
        pa0 = A + (size_t)t0 * K + kq;
        pa1 = A + (size_t)t1 * K + kq;
    } else {
        pa0 = A + (size_t)(m0 + lrow) * K + kq;
        pa1 = A + (size_t)(m0 + lrow + 64) * K + kq;
    }
    const float* pb0 = B + (size_t)(n0 + lrow) * K + kq;
    const float* pb1 = B + (size_t)(n0 + lrow + 64) * K + kq;

    float acc[4][4][4];
#pragma unroll
    for (int i = 0; i < 4; i++)
#pragma unroll
        for (int j = 0; j < 4; j++)
#pragma unroll
            for (int q = 0; q < 4; q++) acc[i][j][q] = 0.f;

    const int KT = K / BK;
    float4 ra0 = *(const float4*)pa0;
    float4 ra1 = *(const float4*)pa1;
    float4 rb0 = *(const float4*)pb0;
    float4 rb1 = *(const float4*)pb1;

    for (int kt = 0; kt < KT; kt++) {
        const int b = kt & 1;
        // store staged regs -> smem (transposed, tf32-converted)
        As[b][kq + 0][lrow] = f2tf32(ra0.x);
        As[b][kq + 1][lrow] = f2tf32(ra0.y);
        As[b][kq + 2][lrow] = f2tf32(ra0.z);
        As[b][kq + 3][lrow] = f2tf32(ra0.w);
        As[b][kq + 0][lrow + 64] = f2tf32(ra1.x);
        As[b][kq + 1][lrow + 64] = f2tf32(ra1.y);
        As[b][kq + 2][lrow + 64] = f2tf32(ra1.z);
        As[b][kq + 3][lrow + 64] = f2tf32(ra1.w);
        Bs[b][kq + 0][lrow] = f2tf32(rb0.x);
        Bs[b][kq + 1][lrow] = f2tf32(rb0.y);
        Bs[b][kq + 2][lrow] = f2tf32(rb0.z);
        Bs[b][kq + 3][lrow] = f2tf32(rb0.w);
        Bs[b][kq + 0][lrow + 64] = f2tf32(rb1.x);
        Bs[b][kq + 1][lrow + 64] = f2tf32(rb1.y);
        Bs[b][kq + 2][lrow + 64] = f2tf32(rb1.z);
        Bs[b][kq + 3][lrow + 64] = f2tf32(rb1.w);

        // issue next tile's global loads (overlap with compute below)
        if (kt + 1 < KT) {
            pa0 += BK; pa1 += BK; pb0 += BK; pb1 += BK;
            ra0 = *(const float4*)pa0;
            ra1 = *(const float4*)pa1;
            rb0 = *(const float4*)pb0;
            rb1 = *(const float4*)pb1;
        }
        __syncthreads();

#pragma unroll
        for (int k8 = 0; k8 < BK; k8 += 8) {
            uint32_t af[4][4], bf[4][2];
#pragma unroll
            for (int mt = 0; mt < 4; mt++) {
                const int m = warpM + mt * 16 + g;
                af[mt][0] = As[b][k8 + tg][m];
                af[mt][1] = As[b][k8 + tg][m + 8];
                af[mt][2] = As[b][k8 + tg + 4][m];
                af[mt][3] = As[b][k8 + tg + 4][m + 8];
            }
#pragma unroll
            for (int nt = 0; nt < 4; nt++) {
                const int n = warpN + nt * 8 + g;
                bf[nt][0] = Bs[b][k8 + tg][n];
                bf[nt][1] = Bs[b][k8 + tg + 4][n];
            }
#pragma unroll
            for (int mt = 0; mt < 4; mt++)
#pragma unroll
                for (int nt = 0; nt < 4; nt++) {
                    asm volatile(
                        "mma.sync.aligned.m16n8k8.row.col.f32.tf32.tf32.f32 "
                        "{%0,%1,%2,%3},{%4,%5,%6,%7},{%8,%9},{%0,%1,%2,%3};\n"
                        : "+f"(acc[mt][nt][0]), "+f"(acc[mt][nt][1]),
                          "+f"(acc[mt][nt][2]), "+f"(acc[mt][nt][3])
                        : "r"(af[mt][0]), "r"(af[mt][1]), "r"(af[mt][2]), "r"(af[mt][3]),
                          "r"(bf[nt][0]), "r"(bf[nt][1]));
                }
        }
        __syncthreads();
    }

    // epilogue
#pragma unroll
    for (int mt = 0; mt < 4; mt++) {
#pragma unroll
        for (int nt = 0; nt < 4; nt++) {
            const int r0 = m0 + warpM + mt * 16 + g;
            const int cc = n0 + warpN + nt * 8 + tg * 2;
            float2 v0 = make_float2(acc[mt][nt][0], acc[mt][nt][1]);
            float2 v1 = make_float2(acc[mt][nt][2], acc[mt][nt][3]);
            if (bias) {
                const float2 bb = *(const float2*)(bias + cc);
                v0.x += bb.x; v0.y += bb.y; v1.x += bb.x; v1.y += bb.y;
            }
            if (bias2) {
                const float2 bb = *(const float2*)(bias2 + cc);
                v0.x += bb.x; v0.y += bb.y; v1.x += bb.x; v1.y += bb.y;
            }
            if (D) {
                const float2 d0 = *(const float2*)(D + (size_t)r0 * N + cc);
                const float2 d1 = *(const float2*)(D + (size_t)(r0 + 8) * N + cc);
                v0.x += d0.x; v0.y += d0.y; v1.x += d1.x; v1.y += d1.y;
            }
            *(float2*)(C + (size_t)r0 * N + cc) = v0;
            *(float2*)(C + (size_t)(r0 + 8) * N + cc) = v1;
        }
    }
}

// ---------------------------------------------------------------------------
__global__ void zero_hc()
{
    const int i = blockIdx.x * blockDim.x + threadIdx.x;
    d_h[i] = 0.f;
    d_c[i] = 0.f;
}

__device__ __forceinline__ float sigf(float x)  { return 1.f / (1.f + __expf(-x)); }
__device__ __forceinline__ float tanhff(float x) { return 2.f / (1.f + __expf(-2.f * x)) - 1.f; }

__global__ void __launch_bounds__(256)
lstm_update(const int* __restrict__ lengths, int t)
{
    const int idx4 = blockIdx.x * blockDim.x + threadIdx.x;  // 0..65535 float4 slots
    const int p  = idx4 >> 8;     // 256 float4 per path
    const int j4 = idx4 & 255;
    const float4* g = (const float4*)(d_gates + (size_t)p * G4);
    const float4 ig = g[j4];
    const float4 fg = g[j4 + 256];
    const float4 gg = g[j4 + 512];
    const float4 og = g[j4 + 768];
    float4 c = ((const float4*)d_c)[idx4];
    float4 h;
    c.x = sigf(fg.x) * c.x + sigf(ig.x) * tanhff(gg.x);
    c.y = sigf(fg.y) * c.y + sigf(ig.y) * tanhff(gg.y);
    c.z = sigf(fg.z) * c.z + sigf(ig.z) * tanhff(gg.z);
    c.w = sigf(fg.w) * c.w + sigf(ig.w) * tanhff(gg.w);
    h.x = sigf(og.x) * tanhff(c.x);
    h.y = sigf(og.y) * tanhff(c.y);
    h.z = sigf(og.z) * tanhff(c.z);
    h.w = sigf(og.w) * tanhff(c.w);
    ((float4*)d_c)[idx4] = c;
    ((float4*)d_h)[idx4] = h;
    if (lengths[p] - 1 == t) ((float4*)d_fh)[idx4] = h;
}

// maxpool over P paths + final linear (OUT=2) + sigmoid
__global__ void __launch_bounds__(1024)
pool_out(const float* __restrict__ Wlin, const float* __restrict__ blin,
         float* __restrict__ out)
{
    const int j = threadIdx.x;  // 0..1023
    float m = -INFINITY;
#pragma unroll 8
    for (int p = 0; p < PP; p++)
        m = fmaxf(m, d_attn[p * HDIM + j]);

    __shared__ float s0[1024];
    __shared__ float s1[1024];
    s0[j] = m * Wlin[j];
    s1[j] = m * Wlin[HDIM + j];
    __syncthreads();
    for (int s = 512; s > 0; s >>= 1) {
        if (j < s) { s0[j] += s0[j + s]; s1[j] += s1[j + s]; }
        __syncthreads();
    }
    if (j == 0) {
        out[0] = 1.f / (1.f + expf(-(s0[0] + blin[0])));
        out[1] = 1.f / (1.f + expf(-(s1[0] + blin[1])));
    }
}

// ---------------------------------------------------------------------------
extern "C" void kernel_launch(void* const* d_in, const int* in_sizes, int n_in,
                              void* d_out, int out_size)
{
    const int*   paths  = (const int*)  d_in[0];
    const int*   lens   = (const int*)  d_in[1];
    const float* emb    = (const float*)d_in[2];
    const float* W_ih   = (const float*)d_in[3];
    const float* W_hh   = (const float*)d_in[4];
    const float* b_ih   = (const float*)d_in[5];
    const float* b_hh   = (const float*)d_in[6];
    const float* W_in   = (const float*)d_in[7];
    const float* b_in   = (const float*)d_in[8];
    const float* W_out  = (const float*)d_in[9];
    const float* b_out  = (const float*)d_in[10];
    const float* W_lin  = (const float*)d_in[11];
    const float* b_lin  = (const float*)d_in[12];
    float* out = (float*)d_out;

    float *gx, *gates, *h, *fh, *v, *attn;
    cudaGetSymbolAddress((void**)&gx,    d_gx);
    cudaGetSymbolAddress((void**)&gates, d_gates);
    cudaGetSymbolAddress((void**)&h,     d_h);
    cudaGetSymbolAddress((void**)&fh,    d_fh);
    cudaGetSymbolAddress((void**)&v,     d_v);
    cudaGetSymbolAddress((void**)&attn,  d_attn);

    const dim3 blk(NTHREADS);

    // init state
    zero_hc<<<(PP * HDIM) / 256, 256>>>();

    // Precompute gx[l*PP+p][:] = emb[paths[p][l]] @ W_ih^T + (b_ih + b_hh)
    gemm_tf32_nt<<<dim3(G4 / BN, (LMAX * PP) / BM), blk>>>(
        emb, W_ih, gx, LMAX * PP, G4, IDIM, b_ih, b_hh, nullptr, paths, lens);

    // Recurrence: 64 sequential steps: gates = h @ W_hh^T + gx[t]; cell update
    for (int t = 0; t < LMAX; t++) {
        gemm_tf32_nt<<<dim3(G4 / BN, PP / BM), blk>>>(
            h, W_hh, gates, PP, G4, HDIM, nullptr, nullptr,
            gx + (size_t)t * PP * G4, nullptr, nullptr);
        lstm_update<<<(PP * HDIM / 4) / 256, 256>>>(lens, t);
    }

    // Degenerate attention (seq_len=1 => softmax of 1x1 => ctx == v):
    // v = final_h @ W_v^T + b_v   (W_v = rows [2H,3H) of W_in)
    gemm_tf32_nt<<<dim3(HDIM / BN, PP / BM), blk>>>(
        fh, W_in + (size_t)2 * HDIM * HDIM, v, PP, HDIM, HDIM,
        b_in + 2 * HDIM, nullptr, nullptr, nullptr, nullptr);

    // attn_out = v @ W_out^T + b_out
    gemm_tf32_nt<<<dim3(HDIM / BN, PP / BM), blk>>>(
        v, W_out, attn, PP, HDIM, HDIM, b_out, nullptr, nullptr, nullptr, nullptr);

    // maxpool over paths + final linear + sigmoid
    pool_out<<<1, 1024>>>(W_lin, b_lin, out);
}

// round 4
// speedup vs baseline: 1.8841x; 1.4020x over previous
#include <cuda_runtime.h>
#include <math.h>
#include <stdint.h>

// Problem constants
#define PP    256      // num paths (batch)
#define LMAX  64       // max path length
#define IDIM  512      // input dim
#define HDIM  1024     // hidden dim
#define G4    4096     // 4*H gates

#define NTHREADS 256
#define NBLK_REC 128   // persistent recurrence grid: 4 (M) x 32 (N) CTAs

// gate interleave: column n of interleaved gates <- row perm(n) of torch-layout W
// n = j*4 + gate  ->  perm(n) = gate*1024 + j
#define PERM(n) ((((n) & 3) << 10) | ((n) >> 2))

// ---------------- device scratch (no runtime allocation allowed) ----------------
__device__ float d_gx[(size_t)LMAX * PP * G4];   // x_t @ W_ih^T + b, gate-interleaved cols
__device__ float d_hbuf[2][PP * HDIM];           // ping-pong h state
__device__ float d_fh[PP * HDIM];
__device__ float d_v[PP * HDIM];
__device__ float d_attn[PP * HDIM];
__device__ unsigned bar_count_g;
__device__ unsigned bar_sense_g;

__device__ __forceinline__ uint32_t f2tf32(float x) {
    uint32_t u;
    asm("cvt.rna.tf32.f32 %0, %1;" : "=r"(u) : "f"(x));
    return u;
}
__device__ __forceinline__ float sigf(float x)   { return 1.f / (1.f + __expf(-x)); }
__device__ __forceinline__ float tanhff(float x) { return 2.f / (1.f + __expf(-2.f * x)) - 1.f; }

__device__ __forceinline__ void mma_tf32(float* acc, const uint32_t* a, const uint32_t* b) {
    asm volatile(
        "mma.sync.aligned.m16n8k8.row.col.f32.tf32.tf32.f32 "
        "{%0,%1,%2,%3},{%4,%5,%6,%7},{%8,%9},{%0,%1,%2,%3};\n"
        : "+f"(acc[0]), "+f"(acc[1]), "+f"(acc[2]), "+f"(acc[3])
        : "r"(a[0]), "r"(a[1]), "r"(a[2]), "r"(a[3]), "r"(b[0]), "r"(b[1]));
}

// ---------------------------------------------------------------------------
// Generic NT GEMM via tf32 mma (tile 128x128, 256 thr). Used for the big
// precompute (with embedding gather + permuted B rows/bias) and projections.
// ---------------------------------------------------------------------------
__global__ void __launch_bounds__(NTHREADS, 1)
gemm_tf32_nt(const float* __restrict__ A, const float* __restrict__ B,
             float* __restrict__ C, int M, int N, int K,
             const float* __restrict__ bias, const float* __restrict__ bias2,
             int permB,
             const int* __restrict__ paths, const int* __restrict__ lengths)
{
    __shared__ uint32_t As[2][16][128 + 4];
    __shared__ uint32_t Bs[2][16][128 + 4];
    __shared__ int need;

    const int tid = threadIdx.x;
    const int m0 = blockIdx.y * 128;
    const int n0 = blockIdx.x * 128;

    if (paths != nullptr) {
        const int l  = m0 / PP;
        const int p0 = m0 % PP;
        if (tid == 0) need = 0;
        __syncthreads();
        if (tid < 128 && lengths[p0 + tid] > l) need = 1;
        __syncthreads();
        if (!need) return;
    }

    const int wid = tid >> 5, lane = tid & 31;
    const int warpM = (wid & 1) * 64, warpN = (wid >> 1) * 32;
    const int g = lane >> 2, tg = lane & 3;

    const int lrow = tid >> 2;
    const int kq = (tid & 3) * 4;
    const float *pa0, *pa1;
    if (paths != nullptr) {
        const int r0 = m0 + lrow, r1 = m0 + lrow + 64;
        const int t0 = paths[(r0 % PP) * LMAX + (r0 / PP)];
        const int t1 = paths[(r1 % PP) * LMAX + (r1 / PP)];
        pa0 = A + (size_t)t0 * K + kq;
        pa1 = A + (size_t)t1 * K + kq;
    } else {
        pa0 = A + (size_t)(m0 + lrow) * K + kq;
        pa1 = A + (size_t)(m0 + lrow + 64) * K + kq;
    }
    const int bn0 = permB ? PERM(n0 + lrow) : (n0 + lrow);
    const int bn1 = permB ? PERM(n0 + lrow + 64) : (n0 + lrow + 64);
    const float* pb0 = B + (size_t)bn0 * K + kq;
    const float* pb1 = B + (size_t)bn1 * K + kq;

    float acc[4][4][4];
#pragma unroll
    for (int i = 0; i < 4; i++)
#pragma unroll
        for (int j = 0; j < 4; j++)
#pragma unroll
            for (int q = 0; q < 4; q++) acc[i][j][q] = 0.f;

    const int KT = K / 16;
    float4 ra0 = *(const float4*)pa0;
    float4 ra1 = *(const float4*)pa1;
    float4 rb0 = *(const float4*)pb0;
    float4 rb1 = *(const float4*)pb1;

    for (int kt = 0; kt < KT; kt++) {
        const int b = kt & 1;
        As[b][kq + 0][lrow] = f2tf32(ra0.x); As[b][kq + 1][lrow] = f2tf32(ra0.y);
        As[b][kq + 2][lrow] = f2tf32(ra0.z); As[b][kq + 3][lrow] = f2tf32(ra0.w);
        As[b][kq + 0][lrow + 64] = f2tf32(ra1.x); As[b][kq + 1][lrow + 64] = f2tf32(ra1.y);
        As[b][kq + 2][lrow + 64] = f2tf32(ra1.z); As[b][kq + 3][lrow + 64] = f2tf32(ra1.w);
        Bs[b][kq + 0][lrow] = f2tf32(rb0.x); Bs[b][kq + 1][lrow] = f2tf32(rb0.y);
        Bs[b][kq + 2][lrow] = f2tf32(rb0.z); Bs[b][kq + 3][lrow] = f2tf32(rb0.w);
        Bs[b][kq + 0][lrow + 64] = f2tf32(rb1.x); Bs[b][kq + 1][lrow + 64] = f2tf32(rb1.y);
        Bs[b][kq + 2][lrow + 64] = f2tf32(rb1.z); Bs[b][kq + 3][lrow + 64] = f2tf32(rb1.w);

        if (kt + 1 < KT) {
            pa0 += 16; pa1 += 16; pb0 += 16; pb1 += 16;
            ra0 = *(const float4*)pa0; ra1 = *(const float4*)pa1;
            rb0 = *(const float4*)pb0; rb1 = *(const float4*)pb1;
        }
        __syncthreads();

#pragma unroll
        for (int k8 = 0; k8 < 16; k8 += 8) {
            uint32_t af[4][4], bf[4][2];
#pragma unroll
            for (int mt = 0; mt < 4; mt++) {
                const int m = warpM + mt * 16 + g;
                af[mt][0] = As[b][k8 + tg][m];     af[mt][1] = As[b][k8 + tg][m + 8];
                af[mt][2] = As[b][k8 + tg + 4][m]; af[mt][3] = As[b][k8 + tg + 4][m + 8];
            }
#pragma unroll
            for (int nt = 0; nt < 4; nt++) {
                const int n = warpN + nt * 8 + g;
                bf[nt][0] = Bs[b][k8 + tg][n];
                bf[nt][1] = Bs[b][k8 + tg + 4][n];
            }
#pragma unroll
            for (int mt = 0; mt < 4; mt++)
#pragma unroll
                for (int nt = 0; nt < 4; nt++)
                    mma_tf32(acc[mt][nt], af[mt], bf[nt]);
        }
        __syncthreads();
    }

#pragma unroll
    for (int mt = 0; mt < 4; mt++) {
#pragma unroll
        for (int nt = 0; nt < 4; nt++) {
            const int r0 = m0 + warpM + mt * 16 + g;
            const int cc = n0 + warpN + nt * 8 + tg * 2;
            float2 v0 = make_float2(acc[mt][nt][0], acc[mt][nt][1]);
            float2 v1 = make_float2(acc[mt][nt][2], acc[mt][nt][3]);
            if (bias) {
                const int c0 = permB ? PERM(cc) : cc;
                const int c1 = permB ? PERM(cc + 1) : (cc + 1);
                float b0 = bias[c0], b1 = bias[c1];
                if (bias2) { b0 += bias2[c0]; b1 += bias2[c1]; }
                v0.x += b0; v0.y += b1; v1.x += b0; v1.y += b1;
            }
            *(float2*)(C + (size_t)r0 * N + cc) = v0;
            *(float2*)(C + (size_t)(r0 + 8) * N + cc) = v1;
        }
    }
}

// ---------------------------------------------------------------------------
__global__ void zero_bar()
{
    bar_count_g = 0u;
    bar_sense_g = 0u;
}

// ---------------------------------------------------------------------------
// Persistent fused LSTM recurrence. Grid = 4(M) x 32(N) = 128 CTAs (all
// co-resident on 148 SMs). Tile 64x128 of interleaved gates. c-state lives in
// registers across all 64 timesteps; h ping-pongs via global buffers (cg ops);
// sense-reversal grid barrier between steps.
// ---------------------------------------------------------------------------
__global__ void __launch_bounds__(NTHREADS, 1)
lstm_persistent(const float* __restrict__ Whh, const int* __restrict__ lengths)
{
    __shared__ uint32_t As[2][16][64 + 4];
    __shared__ uint32_t Bs[2][16][128 + 4];

    const int tid = threadIdx.x, wid = tid >> 5, lane = tid & 31;
    const int m0 = blockIdx.y * 64;     // path rows
    const int n0 = blockIdx.x * 128;    // interleaved gate cols
    const int warpM = (wid & 1) * 32, warpN = (wid >> 1) * 32;
    const int g = lane >> 2, tg = lane & 3;
    const bool even = (tg & 1) == 0;

    const int lrow = tid >> 2;          // 0..63
    const int kq = (tid & 3) * 4;

    // W_hh row pointers (perm applied at index), fixed across steps
    const float* pb0_base = Whh + (size_t)PERM(n0 + lrow) * HDIM + kq;
    const float* pb1_base = Whh + (size_t)PERM(n0 + lrow + 64) * HDIM + kq;

    // epilogue rows + lengths (4 rows per thread: mt x rh)
    int rows[2][2], lens[2][2];
#pragma unroll
    for (int mt = 0; mt < 2; mt++)
#pragma unroll
        for (int rh = 0; rh < 2; rh++) {
            rows[mt][rh] = m0 + warpM + mt * 16 + g + rh * 8;
            lens[mt][rh] = lengths[rows[mt][rh]];
        }
    // j column for even lanes (1 j per (nt)); odd lanes mirror via shuffle
    int jcol[4];
#pragma unroll
    for (int nt = 0; nt < 4; nt++)
        jcol[nt] = (n0 + warpN + nt * 8 + tg * 2) >> 2;

    float creg[2][4][2];
#pragma unroll
    for (int mt = 0; mt < 2; mt++)
#pragma unroll
        for (int nt = 0; nt < 4; nt++)
            creg[mt][nt][0] = creg[mt][nt][1] = 0.f;

    unsigned sense = 0;

    for (int t = 0; t < LMAX; t++) {
        const float* __restrict__ hsrc = d_hbuf[t & 1];
        float* __restrict__ hdst = d_hbuf[(t + 1) & 1];
        const float* __restrict__ gxt = d_gx + (size_t)t * PP * G4;

        // init accumulators from precomputed input-side gates
        float acc[2][4][4];
#pragma unroll
        for (int mt = 0; mt < 2; mt++)
#pragma unroll
            for (int nt = 0; nt < 4; nt++) {
                const float* base = gxt + (size_t)(m0 + warpM + mt * 16 + g) * G4
                                        + (n0 + warpN + nt * 8 + tg * 2);
                const float2 v0 = *(const float2*)base;
                const float2 v1 = *(const float2*)(base + (size_t)8 * G4);
                acc[mt][nt][0] = v0.x; acc[mt][nt][1] = v0.y;
                acc[mt][nt][2] = v1.x; acc[mt][nt][3] = v1.y;
            }

        if (t > 0) {   // h==0 at t=0 contributes nothing
            const float* pa  = hsrc + (size_t)(m0 + lrow) * HDIM + kq;
            const float* pb0 = pb0_base;
            const float* pb1 = pb1_base;
            float4 ra  = __ldcg((const float4*)pa);
            float4 rb0 = *(const float4*)pb0;
            float4 rb1 = *(const float4*)pb1;

            for (int kt = 0; kt < HDIM / 16; kt++) {
                const int b = kt & 1;
                As[b][kq + 0][lrow] = f2tf32(ra.x); As[b][kq + 1][lrow] = f2tf32(ra.y);
                As[b][kq + 2][lrow] = f2tf32(ra.z); As[b][kq + 3][lrow] = f2tf32(ra.w);
                Bs[b][kq + 0][lrow] = f2tf32(rb0.x); Bs[b][kq + 1][lrow] = f2tf32(rb0.y);
                Bs[b][kq + 2][lrow] = f2tf32(rb0.z); Bs[b][kq + 3][lrow] = f2tf32(rb0.w);
                Bs[b][kq + 0][lrow + 64] = f2tf32(rb1.x); Bs[b][kq + 1][lrow + 64] = f2tf32(rb1.y);
                Bs[b][kq + 2][lrow + 64] = f2tf32(rb1.z); Bs[b][kq + 3][lrow + 64] = f2tf32(rb1.w);

                if (kt + 1 < HDIM / 16) {
                    pa += 16; pb0 += 16; pb1 += 16;
                    ra  = __ldcg((const float4*)pa);
                    rb0 = *(const float4*)pb0;
                    rb1 = *(const float4*)pb1;
                }
                __syncthreads();

#pragma unroll
                for (int k8 = 0; k8 < 16; k8 += 8) {
                    uint32_t af[2][4], bf[4][2];
#pragma unroll
                    for (int mt = 0; mt < 2; mt++) {
                        const int m = warpM + mt * 16 + g;
                        af[mt][0] = As[b][k8 + tg][m];     af[mt][1] = As[b][k8 + tg][m + 8];
                        af[mt][2] = As[b][k8 + tg + 4][m]; af[mt][3] = As[b][k8 + tg + 4][m + 8];
                    }
#pragma unroll
                    for (int nt = 0; nt < 4; nt++) {
                        const int n = warpN + nt * 8 + g;
                        bf[nt][0] = Bs[b][k8 + tg][n];
                        bf[nt][1] = Bs[b][k8 + tg + 4][n];
                    }
#pragma unroll
                    for (int mt = 0; mt < 2; mt++)
#pragma unroll
                        for (int nt = 0; nt < 4; nt++)
                            mma_tf32(acc[mt][nt], af[mt], bf[nt]);
                }
                __syncthreads();
            }
        }

        // fused LSTM cell update: lane pair (tg, tg^1) holds (i,f) / (g,o)
#pragma unroll
        for (int mt = 0; mt < 2; mt++) {
#pragma unroll
            for (int nt = 0; nt < 4; nt++) {
                float oth[4];
#pragma unroll
                for (int q = 0; q < 4; q++)
                    oth[q] = __shfl_xor_sync(0xFFFFFFFFu, acc[mt][nt][q], 1);
#pragma unroll
                for (int rh = 0; rh < 2; rh++) {
                    const float ip = even ? acc[mt][nt][rh * 2 + 0] : oth[rh * 2 + 0];
                    const float fp = even ? acc[mt][nt][rh * 2 + 1] : oth[rh * 2 + 1];
                    const float gp = even ? oth[rh * 2 + 0] : acc[mt][nt][rh * 2 + 0];
                    const float op = even ? oth[rh * 2 + 1] : acc[mt][nt][rh * 2 + 1];
                    const float c = sigf(fp) * creg[mt][nt][rh] + sigf(ip) * tanhff(gp);
                    creg[mt][nt][rh] = c;
                    const float h = sigf(op) * tanhff(c);
                    if (even) {
                        const int row = rows[mt][rh];
                        __stcg(hdst + (size_t)row * HDIM + jcol[nt], h);
                        if (lens[mt][rh] - 1 == t)
                            d_fh[(size_t)row * HDIM + jcol[nt]] = h;
                    }
                }
            }
        }

        // grid-wide barrier (skip after last step)
        if (t < LMAX - 1) {
            const unsigned ns = sense ^ 1u;
            __threadfence();
            __syncthreads();
            if (tid == 0) {
                if (atomicAdd(&bar_count_g, 1u) == NBLK_REC - 1u) {
                    bar_count_g = 0u;
                    __threadfence();
                    *(volatile unsigned*)&bar_sense_g = ns;
                } else {
                    while (*(volatile unsigned*)&bar_sense_g != ns) __nanosleep(64);
                    __threadfence();
                }
            }
            __syncthreads();
            sense = ns;
        }
    }
}

// maxpool over P paths + final linear (OUT=2) + sigmoid
__global__ void __launch_bounds__(1024)
pool_out(const float* __restrict__ Wlin, const float* __restrict__ blin,
         float* __restrict__ out)
{
    const int j = threadIdx.x;
    float m = -INFINITY;
#pragma unroll 8
    for (int p = 0; p < PP; p++)
        m = fmaxf(m, d_attn[p * HDIM + j]);

    __shared__ float s0[1024];
    __shared__ float s1[1024];
    s0[j] = m * Wlin[j];
    s1[j] = m * Wlin[HDIM + j];
    __syncthreads();
    for (int s = 512; s > 0; s >>= 1) {
        if (j < s) { s0[j] += s0[j + s]; s1[j] += s1[j + s]; }
        __syncthreads();
    }
    if (j == 0) {
        out[0] = 1.f / (1.f + expf(-(s0[0] + blin[0])));
        out[1] = 1.f / (1.f + expf(-(s1[0] + blin[1])));
    }
}

// ---------------------------------------------------------------------------
extern "C" void kernel_launch(void* const* d_in, const int* in_sizes, int n_in,
                              void* d_out, int out_size)
{
    const int*   paths  = (const int*)  d_in[0];
    const int*   lens   = (const int*)  d_in[1];
    const float* emb    = (const float*)d_in[2];
    const float* W_ih   = (const float*)d_in[3];
    const float* W_hh   = (const float*)d_in[4];
    const float* b_ih   = (const float*)d_in[5];
    const float* b_hh   = (const float*)d_in[6];
    const float* W_in   = (const float*)d_in[7];
    const float* b_in   = (const float*)d_in[8];
    const float* W_out  = (const float*)d_in[9];
    const float* b_out  = (const float*)d_in[10];
    const float* W_lin  = (const float*)d_in[11];
    const float* b_lin  = (const float*)d_in[12];
    float* out = (float*)d_out;

    float *gx, *fh, *v, *attn;
    cudaGetSymbolAddress((void**)&gx,   d_gx);
    cudaGetSymbolAddress((void**)&fh,   d_fh);
    cudaGetSymbolAddress((void**)&v,    d_v);
    cudaGetSymbolAddress((void**)&attn, d_attn);

    const dim3 blk(NTHREADS);

    zero_bar<<<1, 32>>>();

    // Precompute gate-interleaved gx[t][p][:] = emb[paths[p][t]] @ W_ih^T + b
    gemm_tf32_nt<<<dim3(G4 / 128, (LMAX * PP) / 128), blk>>>(
        emb, W_ih, gx, LMAX * PP, G4, IDIM, b_ih, b_hh, 1, paths, lens);

    // Entire 64-step recurrence in ONE persistent kernel
    lstm_persistent<<<dim3(32, 4), blk>>>(W_hh, lens);

    // Degenerate attention (seq_len=1 => softmax(1x1)=1 => ctx == v):
    gemm_tf32_nt<<<dim3(HDIM / 128, PP / 128), blk>>>(
        fh, W_in + (size_t)2 * HDIM * HDIM, v, PP, HDIM, HDIM,
        b_in + 2 * HDIM, nullptr, 0, nullptr, nullptr);

    gemm_tf32_nt<<<dim3(HDIM / 128, PP / 128), blk>>>(
        v, W_out, attn, PP, HDIM, HDIM, b_out, nullptr, 0, nullptr, nullptr);

    pool_out<<<1, 1024>>>(W_lin, b_lin, out);
}